// round 7
// baseline (speedup 1.0000x reference)
#include <cuda_runtime.h>
#include <math.h>

#define Bv 16
#define Tv 256
#define Hv 512
#define Vv 32
#define NBLK 128
#define NTHR 256

// smem layout (floats)
#define SM_XQ   0
#define SM_RED  25664            // 16*1604 (P3 xq: 16 rows * 401 float4)
#define SM_SG   (25664+4096)
#define SM_SQ   (SM_SG+256)
#define SM_SV   (SM_SQ+512)
#define SM_SW   (SM_SV+512)
#define SM_SST  (SM_SW+32)
#define SMEM_FLOATS (SM_SST+2)

__device__ float g_W0[2048*1536];     // [Wih0 | Whh0]
__device__ float g_W1[2048*1024];     // [Wih1 | Whh1]
__device__ float g_Kproj[Bv*Tv*Hv];
__device__ float g_qp[Bv*Hv];
__device__ float g_scores[Bv*Tv];
__device__ float g_ctx[2][Bv*Hv];
__device__ float g_h[2][2][Bv*Hv];    // [layer][parity][b*H+h]
__device__ unsigned g_arr[NBLK*8];    // padded arrival flags (32B stride)
__device__ unsigned g_gen;            // grid barrier generation (hub-written)
__device__ unsigned g_scnt[Bv];       // sub-barrier counters
__device__ unsigned g_sgen[Bv];       // sub-barrier generations

__device__ __forceinline__ float warp_sum(float v){
#pragma unroll
    for(int o=16;o>0;o>>=1) v += __shfl_xor_sync(0xffffffffu,v,o);
    return v;
}
__device__ __forceinline__ float warp_max(float v){
#pragma unroll
    for(int o=16;o>0;o>>=1) v = fmaxf(v,__shfl_xor_sync(0xffffffffu,v,o));
    return v;
}
__device__ __forceinline__ float sigf(float x){ return 1.0f/(1.0f+expf(-x)); }
__device__ __forceinline__ float tanha(float x){ float y; asm("tanh.approx.f32 %0,%1;":"=f"(y):"f"(x)); return y; }
__device__ __forceinline__ unsigned ld_acq(const unsigned* p){
    unsigned v; asm volatile("ld.acquire.gpu.global.u32 %0,[%1];":"=r"(v):"l"(p):"memory"); return v;
}
__device__ __forceinline__ unsigned atom_add_acqrel(unsigned* p, unsigned v){
    unsigned old; asm volatile("atom.acq_rel.gpu.global.add.u32 %0,[%1],%2;":"=r"(old):"l"(p),"r"(v):"memory"); return old;
}
__device__ __forceinline__ void st_rel(unsigned* p, unsigned v){
    asm volatile("st.release.gpu.global.u32 [%0],%1;"::"l"(p),"r"(v):"memory");
}

// hub grid barrier: contention-free padded-flag arrivals; block 0 scans and
// flips a single generation word; everyone spins 1-thread on the gen line.
__device__ __forceinline__ void grid_barrier(unsigned k, int tid, int blk){
    __syncthreads();
    if(tid==0){
        __threadfence();
        st_rel(&g_arr[blk*8], k);
    }
    if(blk==0 && tid<32){
        for(;;){
            bool ok = ld_acq(&g_arr[(unsigned)tid*8])       >= k
                   && ld_acq(&g_arr[(unsigned)(tid+32)*8])  >= k
                   && ld_acq(&g_arr[(unsigned)(tid+64)*8])  >= k
                   && ld_acq(&g_arr[(unsigned)(tid+96)*8])  >= k;
            if(__all_sync(0xffffffffu, ok)) break;
            __nanosleep(32);
        }
        if(tid==0) st_rel(&g_gen, k);
    }
    if(tid==0){
        while(ld_acq(&g_gen) < k) __nanosleep(32);
    }
    __syncthreads();
}
__device__ __forceinline__ void sub_barrier(unsigned k, int tid, int ab){
    __syncthreads();
    if(tid==0){
        __threadfence();
        unsigned old = atom_add_acqrel(&g_scnt[ab], 1u);
        if(old == k*8u - 1u) st_rel(&g_sgen[ab], k);
        while(ld_acq(&g_sgen[ab]) < k) __nanosleep(32);
    }
    __syncthreads();
}

// ---------- one-time: concatenate LSTM weights ----------
__global__ void wcat_kernel(const float* __restrict__ Wih0, const float* __restrict__ Whh0,
                            const float* __restrict__ Wih1, const float* __restrict__ Whh1){
    const int row = blockIdx.x, tid = threadIdx.x;
    const float4* a0 = (const float4*)(Wih0 + (size_t)row*1024);
    const float4* b0 = (const float4*)(Whh0 + (size_t)row*512);
    float4* d0 = (float4*)(g_W0 + (size_t)row*1536);
#pragma unroll
    for(int i=0;i<2;i++) d0[tid+i*128] = a0[tid+i*128];
    d0[256+tid] = b0[tid];
    const float4* a1 = (const float4*)(Wih1 + (size_t)row*512);
    const float4* b1 = (const float4*)(Whh1 + (size_t)row*512);
    float4* d1 = (float4*)(g_W1 + (size_t)row*1024);
    d1[tid]     = a1[tid];
    d1[128+tid] = b1[tid];
}

// ---------- Kproj = enc @ Wk^T + bk ----------
__global__ void kproj_kernel(const float* __restrict__ enc, const float* __restrict__ Wk,
                             const float* __restrict__ bk){
    __shared__ float As[16][65], Bs[16][65];
    const int bm = blockIdx.x*64, bn = blockIdx.y*64, tid = threadIdx.x;
    const int tm = (tid/16)*4, tn = (tid%16)*4;
    float acc[4][4] = {};
    for(int k0=0;k0<Hv;k0+=16){
        for(int i=tid;i<64*16;i+=NTHR){
            int m=i>>4,k=i&15;
            As[k][m]=enc[(size_t)(bm+m)*Hv+k0+k];
            Bs[k][m]=Wk [(size_t)(bn+m)*Hv+k0+k];
        }
        __syncthreads();
#pragma unroll
        for(int k=0;k<16;k++){
            float a[4],b[4];
#pragma unroll
            for(int x=0;x<4;x++){ a[x]=As[k][tm+x]; b[x]=Bs[k][tn+x]; }
#pragma unroll
            for(int x=0;x<4;x++)
#pragma unroll
                for(int y=0;y<4;y++) acc[x][y]+=a[x]*b[y];
        }
        __syncthreads();
    }
#pragma unroll
    for(int x=0;x<4;x++)
#pragma unroll
        for(int y=0;y<4;y++)
            g_Kproj[(size_t)(bm+tm+x)*Hv+bn+tn+y]=acc[x][y]+bk[bn+tn+y];
}

// ---------- init ----------
__global__ void decoder_init(const float* __restrict__ h0in,
                             const float* __restrict__ Wq, const float* __restrict__ bq){
    const int tid=threadIdx.x, blk=blockIdx.x, gid=blk*NTHR+tid;
    if(gid<Bv*Hv){
        g_h[0][0][gid]=h0in[gid];
        g_h[1][0][gid]=h0in[Bv*Hv+gid];
        g_ctx[0][gid]=0.f; g_ctx[1][gid]=0.f;
    }
    if(gid==0) g_gen=0u;
    if(gid<NBLK) g_arr[gid*8]=0u;
    if(gid<Bv){ g_scnt[gid]=0u; g_sgen[gid]=0u; }
    const int ab=blk>>3, sub=blk&7, wid=tid>>5, lane=tid&31;
    const float4* h14=(const float4*)(h0in+Bv*Hv+ab*Hv);
#pragma unroll
    for(int r=0;r<8;r++){
        const int hrow=sub*64+r*8+wid;
        const float4* wr=(const float4*)(Wq+(size_t)hrow*Hv);
        float acc=0.f;
#pragma unroll
        for(int i=0;i<4;i++){
            float4 w4=wr[i*32+lane], x4=h14[i*32+lane];
            acc+=w4.x*x4.x+w4.y*x4.y+w4.z*x4.z+w4.w*x4.w;
        }
        acc=warp_sum(acc);
        if(lane==0) g_qp[ab*Hv+hrow]=acc+bq[hrow];
    }
}

// ---------- persistent decoder ----------
__global__ void __launch_bounds__(NTHR,1)
decoder_main(const float* __restrict__ enc, const float* __restrict__ c0in,
             const float* __restrict__ Wq, const float* __restrict__ bq,
             const float* __restrict__ v,  const float* __restrict__ vb,
             const float* __restrict__ bih0, const float* __restrict__ bhh0,
             const float* __restrict__ bih1, const float* __restrict__ bhh1,
             const float* __restrict__ Wout, const float* __restrict__ bout,
             float* __restrict__ out){
    extern __shared__ float sm[];
    float4* xq4 = (float4*)(sm + SM_XQ);

    const int tid=threadIdx.x, blk=blockIdx.x;
    const int wid=tid>>5, lane=tid&31;
    const int ab=blk>>3, sub=blk&7, t0=sub*32;
    unsigned bar_k=1, sub_k=1;

    sm[SM_SV+tid]=v[tid]; sm[SM_SV+tid+256]=v[tid+256];
    const float vb0=vb[0];

    const int kc = tid>>4, rg = (tid>>2)&3, bg = tid&3;
    const int ul64=tid>>4, b64=tid&15, unit64=blk*4+ul64;
    float c0r=0.f, c1r=0.f;
    if(tid<64){
        c0r=c0in[b64*Hv+unit64];
        c1r=c0in[Bv*Hv+b64*Hv+unit64];
    }

    for(int s=0;s<Tv;s++){
        const int p=s&1, pn=p^1;

        // ======== P1: attention scores (ab, t0..t0+31) ========
        sm[SM_SQ+tid]=g_qp[ab*Hv+tid]; sm[SM_SQ+tid+256]=g_qp[ab*Hv+256+tid];
        __syncthreads();
        {
            const float4* sq4=(const float4*)(sm+SM_SQ);
            const float4* sv4=(const float4*)(sm+SM_SV);
#pragma unroll
            for(int r=0;r<4;r++){
                const int t_=t0+r*8+wid;
                const float4* kp4=(const float4*)(g_Kproj+(size_t)(ab*Tv+t_)*Hv);
                float acc=0.f;
#pragma unroll
                for(int i=0;i<4;i++){
                    float4 k4=kp4[i*32+lane], q4=sq4[i*32+lane], vv=sv4[i*32+lane];
                    acc+=vv.x*tanha(q4.x+k4.x)+vv.y*tanha(q4.y+k4.y)
                        +vv.z*tanha(q4.z+k4.z)+vv.w*tanha(q4.w+k4.w);
                }
                acc=warp_sum(acc);
                if(lane==0) g_scores[ab*Tv+t_]=acc+vb0;
            }
        }
        sub_barrier(sub_k, tid, ab); sub_k++;

        // ======== P2: softmax + partial ctx ========
        if(wid==0){
            float scv[8], m=-1e30f;
#pragma unroll
            for(int j=0;j<8;j++){ scv[j]=g_scores[ab*Tv+lane+j*32]; m=fmaxf(m,scv[j]); }
            m=warp_max(m);
            float su=0.f;
#pragma unroll
            for(int j=0;j<8;j++) su+=expf(scv[j]-m);
            su=warp_sum(su);
            if(lane==0){ sm[SM_SST]=m; sm[SM_SST+1]=su; }
        }
        if(tid<64) g_ctx[pn][blk*64+tid]=0.f;
        __syncthreads();
        if(tid<32) sm[SM_SW+tid]=expf(g_scores[ab*Tv+t0+tid]-sm[SM_SST])/sm[SM_SST+1];
        __syncthreads();
        {
            const int h2=tid*2;
            float a0=0.f,a1=0.f;
#pragma unroll 8
            for(int j=0;j<32;j++){
                const float wj=sm[SM_SW+j];
                const float2 e2=*(const float2*)(enc+(size_t)(ab*Tv+t0+j)*Hv+h2);
                a0+=wj*e2.x; a1+=wj*e2.y;
            }
            atomicAdd(&g_ctx[p][ab*Hv+h2],a0);
            atomicAdd(&g_ctx[p][ab*Hv+h2+1],a1);
        }

        // ---- pre-stage barrier-independent parts of P3's x (enc, h0_old) ----
        {
            const float4* h0p=(const float4*)g_h[0][p];
            for(int idx=tid; idx<2048; idx+=NTHR){           // enc: k4g 0..127
                const int b_=idx>>7, k4g=idx&127;
                const int kcs=k4g/24, k4=k4g-kcs*24;
                xq4[b_*401+kcs*25+k4]=*(const float4*)(enc+(size_t)(b_*Tv+s)*Hv+k4g*4);
            }
            for(int idx=tid; idx<2048; idx+=NTHR){           // h0_old: k4g 256..383
                const int b_=idx>>7, k4g=256+(idx&127);
                const int kcs=k4g/24, k4=k4g-kcs*24;
                xq4[b_*401+kcs*25+k4]=h0p[b_*128+(idx&127)];
            }
        }
        grid_barrier(bar_k, tid, blk); bar_k++;

        // ======== P3: LSTM layer 0, K=1536 ========
        {
            const float4* ctx=(const float4*)g_ctx[p];
            for(int idx=tid; idx<2048; idx+=NTHR){           // ctx: k4g 128..255
                const int b_=idx>>7, k4g=128+(idx&127);
                const int kcs=k4g/24, k4=k4g-kcs*24;
                xq4[b_*401+kcs*25+k4]=ctx[b_*128+(idx&127)];
            }
        }
        __syncthreads();
        {
            const float4* wb=(const float4*)g_W0 + (size_t)(rg*512+blk*4)*384 + kc*24;
            const float4* xb=xq4 + (bg*4)*401 + kc*25;
            float acc[4][4]={};
#pragma unroll 4
            for(int k4=0;k4<24;k4++){
                float4 xv[4], wv[4];
#pragma unroll
                for(int j=0;j<4;j++) xv[j]=xb[j*401+k4];
#pragma unroll
                for(int i=0;i<4;i++) wv[i]=wb[(size_t)i*384+k4];
#pragma unroll
                for(int i=0;i<4;i++)
#pragma unroll
                    for(int j=0;j<4;j++)
                        acc[i][j]+=wv[i].x*xv[j].x+wv[i].y*xv[j].y+wv[i].z*xv[j].z+wv[i].w*xv[j].w;
            }
            float* red = sm+SM_RED+kc*256;
#pragma unroll
            for(int i=0;i<4;i++)
                *(float4*)(red+(rg*4+i)*16+bg*4)=make_float4(acc[i][0],acc[i][1],acc[i][2],acc[i][3]);
        }
        __syncthreads();
        {
            const int r16=tid>>4, b_=tid&15;
            float g=0.f;
#pragma unroll
            for(int kk=0;kk<16;kk++) g+=sm[SM_RED+kk*256+r16*16+b_];
            const int grow=(r16>>2)*512+blk*4+(r16&3);
            sm[SM_SG+tid]=g+bih0[grow]+bhh0[grow];
        }
        __syncthreads();
        if(tid<64){
            const float gi=sm[SM_SG+(0+ul64)*16+b64], gf=sm[SM_SG+(4+ul64)*16+b64];
            const float gg=sm[SM_SG+(8+ul64)*16+b64], go=sm[SM_SG+(12+ul64)*16+b64];
            c0r=sigf(gf)*c0r+sigf(gi)*tanhf(gg);
            g_h[0][pn][b64*Hv+unit64]=sigf(go)*tanhf(c0r);
        }
        __syncthreads();
        // ---- pre-stage h1_old part of P4's x ----
        {
            const float4* h1o=(const float4*)g_h[1][p];
            for(int idx=tid; idx<2048; idx+=NTHR){           // k4g 128..255
                const int b_=idx>>7, k4g=128+(idx&127);
                const int kcs=k4g>>4, k4=k4g&15;
                xq4[b_*273+kcs*17+k4]=h1o[b_*128+(idx&127)];
            }
        }
        grid_barrier(bar_k, tid, blk); bar_k++;

        // ======== P4: LSTM layer 1, K=1024 ========
        {
            const float4* h0n=(const float4*)g_h[0][pn];
            for(int idx=tid; idx<2048; idx+=NTHR){           // k4g 0..127
                const int b_=idx>>7, k4g=idx&127;
                const int kcs=k4g>>4, k4=k4g&15;
                xq4[b_*273+kcs*17+k4]=h0n[b_*128+k4g];
            }
        }
        __syncthreads();
        {
            const float4* wb=(const float4*)g_W1 + (size_t)(rg*512+blk*4)*256 + kc*16;
            const float4* xb=xq4 + (bg*4)*273 + kc*17;
            float acc[4][4]={};
#pragma unroll 4
            for(int k4=0;k4<16;k4++){
                float4 xv[4], wv[4];
#pragma unroll
                for(int j=0;j<4;j++) xv[j]=xb[j*273+k4];
#pragma unroll
                for(int i=0;i<4;i++) wv[i]=wb[(size_t)i*256+k4];
#pragma unroll
                for(int i=0;i<4;i++)
#pragma unroll
                    for(int j=0;j<4;j++)
                        acc[i][j]+=wv[i].x*xv[j].x+wv[i].y*xv[j].y+wv[i].z*xv[j].z+wv[i].w*xv[j].w;
            }
            float* red = sm+SM_RED+kc*256;
#pragma unroll
            for(int i=0;i<4;i++)
                *(float4*)(red+(rg*4+i)*16+bg*4)=make_float4(acc[i][0],acc[i][1],acc[i][2],acc[i][3]);
        }
        __syncthreads();
        {
            const int r16=tid>>4, b_=tid&15;
            float g=0.f;
#pragma unroll
            for(int kk=0;kk<16;kk++) g+=sm[SM_RED+kk*256+r16*16+b_];
            const int grow=(r16>>2)*512+blk*4+(r16&3);
            sm[SM_SG+tid]=g+bih1[grow]+bhh1[grow];
        }
        __syncthreads();
        if(tid<64){
            const float gi=sm[SM_SG+(0+ul64)*16+b64], gf=sm[SM_SG+(4+ul64)*16+b64];
            const float gg=sm[SM_SG+(8+ul64)*16+b64], go=sm[SM_SG+(12+ul64)*16+b64];
            c1r=sigf(gf)*c1r+sigf(gi)*tanhf(gg);
            g_h[1][pn][b64*Hv+unit64]=sigf(go)*tanhf(c1r);
        }
        grid_barrier(bar_k, tid, blk); bar_k++;

        // ======== P5: qp (next step) + logits ========
        {
            const int bneed=blk>>3;
            const float4* h1n4=(const float4*)g_h[1][pn];
            if(tid<128) xq4[tid]=h1n4[bneed*128+tid];
            __syncthreads();
#pragma unroll
            for(int j=0;j<8;j++){
                const int h=(blk&7)*64+wid*8+j;
                const float4* wq4=(const float4*)(Wq+(size_t)h*Hv);
                float acc=0.f;
#pragma unroll
                for(int i=0;i<4;i++){
                    float4 w4=wq4[i*32+lane], x4=xq4[i*32+lane];
                    acc+=w4.x*x4.x+w4.y*x4.y+w4.z*x4.z+w4.w*x4.w;
                }
                acc=warp_sum(acc);
                if(lane==0) g_qp[bneed*Hv+h]=acc+bq[h];
            }
            if(wid<4){
                const int vo=(blk&7)*4+wid;
                const float4* wo4=(const float4*)(Wout+(size_t)vo*Hv);
                float acc=0.f;
#pragma unroll
                for(int i=0;i<4;i++){
                    float4 w4=wo4[i*32+lane], x4=xq4[i*32+lane];
                    acc+=w4.x*x4.x+w4.y*x4.y+w4.z*x4.z+w4.w*x4.w;
                }
                acc=warp_sum(acc);
                if(lane==0) out[(size_t)(bneed*Tv+s)*Vv+vo]=acc+bout[vo];
            }
        }
        // qp producers == qp consumers (same 8-block group): sub-barrier suffices
        sub_barrier(sub_k, tid, ab); sub_k++;
    }
}

extern "C" void kernel_launch(void* const* d_in, const int* in_sizes, int n_in,
                              void* d_out, int out_size){
    const float* enc  =(const float*)d_in[0];
    const float* h0in =(const float*)d_in[1];
    const float* c0in =(const float*)d_in[2];
    const float* Wq   =(const float*)d_in[4];
    const float* bq   =(const float*)d_in[5];
    const float* Wk   =(const float*)d_in[6];
    const float* bk   =(const float*)d_in[7];
    const float* v    =(const float*)d_in[8];
    const float* vb   =(const float*)d_in[9];
    const float* Wih0 =(const float*)d_in[10];
    const float* bih0 =(const float*)d_in[11];
    const float* Whh0 =(const float*)d_in[12];
    const float* bhh0 =(const float*)d_in[13];
    const float* Wih1 =(const float*)d_in[14];
    const float* bih1 =(const float*)d_in[15];
    const float* Whh1 =(const float*)d_in[16];
    const float* bhh1 =(const float*)d_in[17];
    const float* Wout =(const float*)d_in[18];
    const float* bout =(const float*)d_in[19];
    float* out=(float*)d_out;

    const int smem_bytes = SMEM_FLOATS*4;
    cudaFuncSetAttribute(decoder_main, cudaFuncAttributeMaxDynamicSharedMemorySize, smem_bytes);

    wcat_kernel<<<2048,128>>>(Wih0,Whh0,Wih1,Whh1);
    kproj_kernel<<<dim3(64,8),NTHR>>>(enc,Wk,bk);
    decoder_init<<<NBLK,NTHR>>>(h0in,Wq,bq);
    decoder_main<<<NBLK,NTHR,smem_bytes>>>(enc,c0in,Wq,bq,v,vb,
        bih0,bhh0,bih1,bhh1,Wout,bout,out);
}

// round 8
// speedup vs baseline: 1.2447x; 1.2447x over previous
#include <cuda_runtime.h>
#include <math.h>

#define Bv 16
#define Tv 256
#define Hv 512
#define Vv 32
#define NBLK 128
#define NTHR 256

// smem layout (floats)
#define SM_W0   0                       // 16 slots * 385 float4 = 24640 f
#define SM_W1   24640                   // 16 slots * 257 float4 = 16448 f
#define SM_RED  41088                   // 4096 f (also P5 h1 stage)
#define SM_SG   45184                   // 256
#define SM_SQ   45440                   // 512
#define SM_SV   45952                   // 512
#define SM_SW   46464                   // 32
#define SM_SST  46496                   // 2
#define SMEM_FLOATS 46498               // 185992 bytes

__device__ float g_Kproj[Bv*Tv*Hv];
__device__ float g_qp[Bv*Hv];
__device__ float g_scores[Bv*Tv];
__device__ float g_ctx[2][Bv*Hv];
__device__ float g_h[2][2][Bv*Hv];      // [layer][parity][b*H+h]
__device__ unsigned g_cnt;              // grid barrier arrival counter
__device__ unsigned g_gen;              // grid barrier generation
__device__ unsigned g_scnt[Bv];
__device__ unsigned g_sgen[Bv];

__device__ __forceinline__ float warp_sum(float v){
#pragma unroll
    for(int o=16;o>0;o>>=1) v += __shfl_xor_sync(0xffffffffu,v,o);
    return v;
}
__device__ __forceinline__ float warp_max(float v){
#pragma unroll
    for(int o=16;o>0;o>>=1) v = fmaxf(v,__shfl_xor_sync(0xffffffffu,v,o));
    return v;
}
__device__ __forceinline__ float sigf(float x){ return 1.0f/(1.0f+expf(-x)); }
__device__ __forceinline__ float tanha(float x){ float y; asm("tanh.approx.f32 %0,%1;":"=f"(y):"f"(x)); return y; }
__device__ __forceinline__ unsigned ld_acq(const unsigned* p){
    unsigned v; asm volatile("ld.acquire.gpu.global.u32 %0,[%1];":"=r"(v):"l"(p):"memory"); return v;
}
__device__ __forceinline__ unsigned atom_add_acqrel(unsigned* p, unsigned v){
    unsigned old; asm volatile("atom.acq_rel.gpu.global.add.u32 %0,[%1],%2;":"=r"(old):"l"(p),"r"(v):"memory"); return old;
}
__device__ __forceinline__ void st_rel(unsigned* p, unsigned v){
    asm volatile("st.release.gpu.global.u32 [%0],%1;"::"l"(p),"r"(v):"memory");
}

// R6 barrier (best measured): atomic counter + separate generation word
__device__ __forceinline__ void grid_barrier(unsigned k, int tid){
    __syncthreads();
    if(tid==0){
        unsigned old = atom_add_acqrel(&g_cnt, 1u);
        if(old == k*(unsigned)NBLK - 1u) st_rel(&g_gen, k);
        while(ld_acq(&g_gen) < k) __nanosleep(32);
    }
    __syncthreads();
}
__device__ __forceinline__ void sub_barrier(unsigned k, int tid, int ab){
    __syncthreads();
    if(tid==0){
        unsigned old = atom_add_acqrel(&g_scnt[ab], 1u);
        if(old == k*8u - 1u) st_rel(&g_sgen[ab], k);
        while(ld_acq(&g_sgen[ab]) < k) __nanosleep(32);
    }
    __syncthreads();
}

// ---------- Kproj = enc @ Wk^T + bk ----------
__global__ void kproj_kernel(const float* __restrict__ enc, const float* __restrict__ Wk,
                             const float* __restrict__ bk){
    __shared__ float As[16][65], Bs[16][65];
    const int bm = blockIdx.x*64, bn = blockIdx.y*64, tid = threadIdx.x;
    const int tm = (tid/16)*4, tn = (tid%16)*4;
    float acc[4][4] = {};
    for(int k0=0;k0<Hv;k0+=16){
        for(int i=tid;i<64*16;i+=NTHR){
            int m=i>>4,k=i&15;
            As[k][m]=enc[(size_t)(bm+m)*Hv+k0+k];
            Bs[k][m]=Wk [(size_t)(bn+m)*Hv+k0+k];
        }
        __syncthreads();
#pragma unroll
        for(int k=0;k<16;k++){
            float a[4],b[4];
#pragma unroll
            for(int x=0;x<4;x++){ a[x]=As[k][tm+x]; b[x]=Bs[k][tn+x]; }
#pragma unroll
            for(int x=0;x<4;x++)
#pragma unroll
                for(int y=0;y<4;y++) acc[x][y]+=a[x]*b[y];
        }
        __syncthreads();
    }
#pragma unroll
    for(int x=0;x<4;x++)
#pragma unroll
        for(int y=0;y<4;y++)
            g_Kproj[(size_t)(bm+tm+x)*Hv+bn+tn+y]=acc[x][y]+bk[bn+tn+y];
}

// ---------- init ----------
__global__ void decoder_init(const float* __restrict__ h0in,
                             const float* __restrict__ Wq, const float* __restrict__ bq){
    const int tid=threadIdx.x, blk=blockIdx.x, gid=blk*NTHR+tid;
    if(gid<Bv*Hv){
        g_h[0][0][gid]=h0in[gid];
        g_h[1][0][gid]=h0in[Bv*Hv+gid];
        g_ctx[0][gid]=0.f; g_ctx[1][gid]=0.f;
    }
    if(gid==0){ g_cnt=0u; g_gen=0u; }
    if(gid<Bv){ g_scnt[gid]=0u; g_sgen[gid]=0u; }
    const int ab=blk>>3, sub=blk&7, wid=tid>>5, lane=tid&31;
    const float4* h14=(const float4*)(h0in+Bv*Hv+ab*Hv);
#pragma unroll
    for(int r=0;r<8;r++){
        const int hrow=sub*64+r*8+wid;
        const float4* wr=(const float4*)(Wq+(size_t)hrow*Hv);
        float acc=0.f;
#pragma unroll
        for(int i=0;i<4;i++){
            float4 w4=wr[i*32+lane], x4=h14[i*32+lane];
            acc+=w4.x*x4.x+w4.y*x4.y+w4.z*x4.z+w4.w*x4.w;
        }
        acc=warp_sum(acc);
        if(lane==0) g_qp[ab*Hv+hrow]=acc+bq[hrow];
    }
}

// ---------- persistent decoder ----------
__global__ void __launch_bounds__(NTHR,1)
decoder_main(const float* __restrict__ enc, const float* __restrict__ c0in,
             const float* __restrict__ Wq, const float* __restrict__ bq,
             const float* __restrict__ v,  const float* __restrict__ vb,
             const float* __restrict__ Wih0, const float* __restrict__ bih0,
             const float* __restrict__ Whh0, const float* __restrict__ bhh0,
             const float* __restrict__ Wih1, const float* __restrict__ bih1,
             const float* __restrict__ Whh1, const float* __restrict__ bhh1,
             const float* __restrict__ Wout, const float* __restrict__ bout,
             float* __restrict__ out){
    extern __shared__ float sm[];
    float4* smW0 = (float4*)(sm + SM_W0);
    float4* smW1 = (float4*)(sm + SM_W1);
    float4* st4  = (float4*)(sm + SM_RED);

    const int tid=threadIdx.x, blk=blockIdx.x;
    const int wid=tid>>5, lane=tid&31;
    const int ab=blk>>3, sub=blk&7, t0=sub*32;
    unsigned bar_k=1, sub_k=1;

    // ---- prologue: load this block's weight slices into smem (once) ----
    for(int idx=tid; idx<16*384; idx+=NTHR){
        const int slot=idx/384, c=idx-slot*384;
        const int u=slot>>2, g=slot&3;
        const int grow=g*512+blk*4+u;
        float4 val = (c<256)? ((const float4*)Wih0)[(size_t)grow*256+c]
                            : ((const float4*)Whh0)[(size_t)grow*128+(c-256)];
        smW0[slot*385+c]=val;
    }
    for(int idx=tid; idx<16*256; idx+=NTHR){
        const int slot=idx>>8, c=idx&255;
        const int u=slot>>2, g=slot&3;
        const int grow=g*512+blk*4+u;
        float4 val = (c<128)? ((const float4*)Wih1)[(size_t)grow*128+c]
                            : ((const float4*)Whh1)[(size_t)grow*128+(c-128)];
        smW1[slot*257+c]=val;
    }
    sm[SM_SV+tid]=v[tid]; sm[SM_SV+tid+256]=v[tid+256];
    const float vb0=vb[0];

    const int kc = tid>>4, rg = (tid>>2)&3, bg = tid&3;
    const int kc24 = kc*24, kc16 = kc*16;
    const int ul64=tid>>4, b64=tid&15, unit64=blk*4+ul64;
    float c0r=0.f, c1r=0.f;
    if(tid<64){
        c0r=c0in[b64*Hv+unit64];
        c1r=c0in[Bv*Hv+b64*Hv+unit64];
    }
    // per-thread bias preload (r16 fixed across steps)
    const int r16=tid>>4, bcol=tid&15;
    const int growB=(r16>>2)*512+blk*4+(r16&3);
    const float bs0=bih0[growB]+bhh0[growB];
    const float bs1=bih1[growB]+bhh1[growB];
    (void)bcol;
    __syncthreads();

    for(int s=0;s<Tv;s++){
        const int p=s&1, pn=p^1;

        // ======== P1: attention scores (ab, t0..t0+31), 4-row-parallel ========
        sm[SM_SQ+tid]=g_qp[ab*Hv+tid]; sm[SM_SQ+tid+256]=g_qp[ab*Hv+256+tid];
        __syncthreads();
        {
            const float4* sq4=(const float4*)(sm+SM_SQ);
            const float4* sv4=(const float4*)(sm+SM_SV);
            const float4* kp[4];
#pragma unroll
            for(int r=0;r<4;r++)
                kp[r]=(const float4*)(g_Kproj+(size_t)(ab*Tv+t0+r*8+wid)*Hv);
            float acc[4]={};
#pragma unroll
            for(int i=0;i<4;i++){
                float4 q4=sq4[i*32+lane], vv=sv4[i*32+lane];
#pragma unroll
                for(int r=0;r<4;r++){
                    float4 k4=kp[r][i*32+lane];
                    acc[r]+=vv.x*tanha(q4.x+k4.x)+vv.y*tanha(q4.y+k4.y)
                          +vv.z*tanha(q4.z+k4.z)+vv.w*tanha(q4.w+k4.w);
                }
            }
#pragma unroll
            for(int r=0;r<4;r++){
                float sres=warp_sum(acc[r]);
                if(lane==0) g_scores[ab*Tv+t0+r*8+wid]=sres+vb0;
            }
        }
        sub_barrier(sub_k, tid, ab); sub_k++;

        // ======== P2: softmax + partial ctx ========
        if(wid==0){
            float scv[8], m=-1e30f;
#pragma unroll
            for(int j=0;j<8;j++){ scv[j]=g_scores[ab*Tv+lane+j*32]; m=fmaxf(m,scv[j]); }
            m=warp_max(m);
            float su=0.f;
#pragma unroll
            for(int j=0;j<8;j++) su+=expf(scv[j]-m);
            su=warp_sum(su);
            if(lane==0){ sm[SM_SST]=m; sm[SM_SST+1]=su; }
        }
        if(tid<64) g_ctx[pn][blk*64+tid]=0.f;
        __syncthreads();
        if(tid<32) sm[SM_SW+tid]=expf(g_scores[ab*Tv+t0+tid]-sm[SM_SST])/sm[SM_SST+1];
        __syncthreads();
        {
            const int h2=tid*2;
            float a0=0.f,a1=0.f;
#pragma unroll 8
            for(int j=0;j<32;j++){
                const float wj=sm[SM_SW+j];
                const float2 e2=*(const float2*)(enc+(size_t)(ab*Tv+t0+j)*Hv+h2);
                a0+=wj*e2.x; a1+=wj*e2.y;
            }
            atomicAdd(&g_ctx[p][ab*Hv+h2],a0);
            atomicAdd(&g_ctx[p][ab*Hv+h2+1],a1);
        }
        grid_barrier(bar_k, tid); bar_k++;

        // ======== P3: LSTM layer 0, K=1536 (weights LDS, x direct-global) ========
        {
            const float4* ep[4];
#pragma unroll
            for(int j=0;j<4;j++)
                ep[j]=(const float4*)(enc+((size_t)((bg*4+j)*Tv+s))*Hv);
            const float4* cp=(const float4*)g_ctx[p];
            const float4* hp=(const float4*)g_h[0][p];
            float acc[4][4]={};
#pragma unroll 8
            for(int k4=0;k4<24;k4++){
                const int kg=kc24+k4;
                float4 xv[4];
#pragma unroll
                for(int j=0;j<4;j++){
                    const int b_=bg*4+j;
                    xv[j]=(kg<128)? ep[j][kg]
                         :(kg<256)? cp[b_*128+(kg-128)]
                                  : hp[b_*128+(kg-256)];
                }
                float4 wv[4];
#pragma unroll
                for(int i=0;i<4;i++) wv[i]=smW0[(i*4+rg)*385+kg];
#pragma unroll
                for(int i=0;i<4;i++)
#pragma unroll
                    for(int j=0;j<4;j++)
                        acc[i][j]+=wv[i].x*xv[j].x+wv[i].y*xv[j].y+wv[i].z*xv[j].z+wv[i].w*xv[j].w;
            }
            float* red = sm+SM_RED+kc*256;
#pragma unroll
            for(int i=0;i<4;i++)
                *(float4*)(red+(rg*4+i)*16+bg*4)=make_float4(acc[i][0],acc[i][1],acc[i][2],acc[i][3]);
        }
        __syncthreads();
        {
            float g=0.f;
#pragma unroll
            for(int kk=0;kk<16;kk++) g+=sm[SM_RED+kk*256+tid];
            sm[SM_SG+tid]=g+bs0;
        }
        __syncthreads();
        if(tid<64){
            const float gi=sm[SM_SG+(0+ul64)*16+b64], gf=sm[SM_SG+(4+ul64)*16+b64];
            const float gg=sm[SM_SG+(8+ul64)*16+b64], go=sm[SM_SG+(12+ul64)*16+b64];
            c0r=sigf(gf)*c0r+sigf(gi)*tanhf(gg);
            g_h[0][pn][b64*Hv+unit64]=sigf(go)*tanhf(c0r);
        }
        grid_barrier(bar_k, tid); bar_k++;

        // ======== P4: LSTM layer 1, K=1024 ========
        {
            const float4* h0n=(const float4*)g_h[0][pn];
            const float4* h1o=(const float4*)g_h[1][p];
            float acc[4][4]={};
#pragma unroll 8
            for(int k4=0;k4<16;k4++){
                const int kg=kc16+k4;
                float4 xv[4];
#pragma unroll
                for(int j=0;j<4;j++){
                    const int b_=bg*4+j;
                    xv[j]=(kg<128)? h0n[b_*128+kg] : h1o[b_*128+(kg-128)];
                }
                float4 wv[4];
#pragma unroll
                for(int i=0;i<4;i++) wv[i]=smW1[(i*4+rg)*257+kg];
#pragma unroll
                for(int i=0;i<4;i++)
#pragma unroll
                    for(int j=0;j<4;j++)
                        acc[i][j]+=wv[i].x*xv[j].x+wv[i].y*xv[j].y+wv[i].z*xv[j].z+wv[i].w*xv[j].w;
            }
            float* red = sm+SM_RED+kc*256;
#pragma unroll
            for(int i=0;i<4;i++)
                *(float4*)(red+(rg*4+i)*16+bg*4)=make_float4(acc[i][0],acc[i][1],acc[i][2],acc[i][3]);
        }
        __syncthreads();
        {
            float g=0.f;
#pragma unroll
            for(int kk=0;kk<16;kk++) g+=sm[SM_RED+kk*256+tid];
            sm[SM_SG+tid]=g+bs1;
        }
        __syncthreads();
        if(tid<64){
            const float gi=sm[SM_SG+(0+ul64)*16+b64], gf=sm[SM_SG+(4+ul64)*16+b64];
            const float gg=sm[SM_SG+(8+ul64)*16+b64], go=sm[SM_SG+(12+ul64)*16+b64];
            c1r=sigf(gf)*c1r+sigf(gi)*tanhf(gg);
            g_h[1][pn][b64*Hv+unit64]=sigf(go)*tanhf(c1r);
        }
        grid_barrier(bar_k, tid); bar_k++;

        // ======== P5: qp (next step, 4-row-parallel) + logits ========
        {
            const int bneed=blk>>3;
            if(tid<128) st4[tid]=((const float4*)g_h[1][pn])[bneed*128+tid];
            __syncthreads();
            const float4* xs4=st4;
#pragma unroll
            for(int jj=0;jj<2;jj++){
                float acc[4]={};
#pragma unroll
                for(int i=0;i<4;i++){
                    float4 x4=xs4[i*32+lane];
#pragma unroll
                    for(int r=0;r<4;r++){
                        const int h=(blk&7)*64+wid*8+jj*4+r;
                        float4 w4=((const float4*)(Wq+(size_t)h*Hv))[i*32+lane];
                        acc[r]+=w4.x*x4.x+w4.y*x4.y+w4.z*x4.z+w4.w*x4.w;
                    }
                }
#pragma unroll
                for(int r=0;r<4;r++){
                    float sres=warp_sum(acc[r]);
                    const int h=(blk&7)*64+wid*8+jj*4+r;
                    if(lane==0) g_qp[bneed*Hv+h]=sres+bq[h];
                }
            }
            if(wid<4){
                const int vo=(blk&7)*4+wid;
                const float4* wo4=(const float4*)(Wout+(size_t)vo*Hv);
                float acc=0.f;
#pragma unroll
                for(int i=0;i<4;i++){
                    float4 w4=wo4[i*32+lane], x4=xs4[i*32+lane];
                    acc+=w4.x*x4.x+w4.y*x4.y+w4.z*x4.z+w4.w*x4.w;
                }
                acc=warp_sum(acc);
                if(lane==0) out[(size_t)(bneed*Tv+s)*Vv+vo]=acc+bout[vo];
            }
        }
        sub_barrier(sub_k, tid, ab); sub_k++;
    }
}

extern "C" void kernel_launch(void* const* d_in, const int* in_sizes, int n_in,
                              void* d_out, int out_size){
    const float* enc  =(const float*)d_in[0];
    const float* h0in =(const float*)d_in[1];
    const float* c0in =(const float*)d_in[2];
    const float* Wq   =(const float*)d_in[4];
    const float* bq   =(const float*)d_in[5];
    const float* Wk   =(const float*)d_in[6];
    const float* bk   =(const float*)d_in[7];
    const float* v    =(const float*)d_in[8];
    const float* vb   =(const float*)d_in[9];
    const float* Wih0 =(const float*)d_in[10];
    const float* bih0 =(const float*)d_in[11];
    const float* Whh0 =(const float*)d_in[12];
    const float* bhh0 =(const float*)d_in[13];
    const float* Wih1 =(const float*)d_in[14];
    const float* bih1 =(const float*)d_in[15];
    const float* Whh1 =(const float*)d_in[16];
    const float* bhh1 =(const float*)d_in[17];
    const float* Wout =(const float*)d_in[18];
    const float* bout =(const float*)d_in[19];
    float* out=(float*)d_out;

    const int smem_bytes = SMEM_FLOATS*4;
    cudaFuncSetAttribute(decoder_main, cudaFuncAttributeMaxDynamicSharedMemorySize, smem_bytes);

    kproj_kernel<<<dim3(64,8),NTHR>>>(enc,Wk,bk);
    decoder_init<<<NBLK,NTHR>>>(h0in,Wq,bq);
    decoder_main<<<NBLK,NTHR,smem_bytes>>>(enc,c0in,Wq,bq,v,vb,
        Wih0,bih0,Whh0,bhh0,Wih1,bih1,Whh1,bhh1,Wout,bout,out);
}

// round 9
// speedup vs baseline: 1.2988x; 1.0435x over previous
#include <cuda_runtime.h>
#include <math.h>

#define Bv 16
#define Tv 256
#define Hv 512
#define Vv 32
#define NBLK 128
#define NTHR 256

// smem layout (floats)
#define SM_W0   0                       // 16 slots * 385 float4 = 24640 f
#define SM_W1   24640                   // 16 slots * 257 float4 = 16448 f
#define SM_RED  41088                   // 2 WG * 2048 f (also P5 h1 stage)
#define SM_SG   45184                   // 2 * 128
#define SM_SQ   45440                   // 2 * 512
#define SM_SV   46464                   // 512 (shared)
#define SM_SW   46976                   // 2 * 16
#define SM_SST  47008                   // 2 * 2
#define SMEM_FLOATS 47012               // 188048 bytes

__device__ float g_Kproj[Bv*Tv*Hv];
__device__ float g_qp[Bv*Hv];
__device__ float g_scores[Bv*Tv];
__device__ float g_ctx[2][Bv*Hv];
__device__ float g_h[2][2][Bv*Hv];      // [layer][parity][b*H+h]
__device__ unsigned g_cnt2[2*32];       // per-WG-set barrier counter (padded)
__device__ unsigned g_gen2[2*32];       // per-WG-set generation (padded)
__device__ unsigned g_scnt[Bv];         // per-batch sub-barrier counters
__device__ unsigned g_sgen[Bv];

__device__ __forceinline__ float warp_sum(float v){
#pragma unroll
    for(int o=16;o>0;o>>=1) v += __shfl_xor_sync(0xffffffffu,v,o);
    return v;
}
__device__ __forceinline__ float warp_max(float v){
#pragma unroll
    for(int o=16;o>0;o>>=1) v = fmaxf(v,__shfl_xor_sync(0xffffffffu,v,o));
    return v;
}
__device__ __forceinline__ float sigf(float x){ return 1.0f/(1.0f+expf(-x)); }
__device__ __forceinline__ float tanha(float x){ float y; asm("tanh.approx.f32 %0,%1;":"=f"(y):"f"(x)); return y; }
__device__ __forceinline__ unsigned ld_acq(const unsigned* p){
    unsigned v; asm volatile("ld.acquire.gpu.global.u32 %0,[%1];":"=r"(v):"l"(p):"memory"); return v;
}
__device__ __forceinline__ unsigned atom_add_acqrel(unsigned* p, unsigned v){
    unsigned old; asm volatile("atom.acq_rel.gpu.global.add.u32 %0,[%1],%2;":"=r"(old):"l"(p),"r"(v):"memory"); return old;
}
__device__ __forceinline__ void st_rel(unsigned* p, unsigned v){
    asm volatile("st.release.gpu.global.u32 [%0],%1;"::"l"(p),"r"(v):"memory");
}
__device__ __forceinline__ void wg_bar(int wg){
    asm volatile("bar.sync %0,%1;"::"r"(1+wg),"r"(128):"memory");
}

// per-WG-set grid barrier across 128 blocks (counter + separate gen word)
__device__ __forceinline__ void grid_barrier_wg(unsigned k, int wg, int wg_tid){
    wg_bar(wg);
    if(wg_tid==0){
        unsigned old = atom_add_acqrel(&g_cnt2[wg*32], 1u);
        if(old == k*(unsigned)NBLK - 1u) st_rel(&g_gen2[wg*32], k);
        while(ld_acq(&g_gen2[wg*32]) < k) __nanosleep(32);
    }
    wg_bar(wg);
}
// per-batch sub-barrier across the 16 block-WGs of one batch
__device__ __forceinline__ void sub_barrier16(unsigned k, int wg, int wg_tid, int b){
    wg_bar(wg);
    if(wg_tid==0){
        unsigned old = atom_add_acqrel(&g_scnt[b], 1u);
        if(old == k*16u - 1u) st_rel(&g_sgen[b], k);
        while(ld_acq(&g_sgen[b]) < k) __nanosleep(32);
    }
    wg_bar(wg);
}

// ---------- Kproj = enc @ Wk^T + bk ----------
__global__ void kproj_kernel(const float* __restrict__ enc, const float* __restrict__ Wk,
                             const float* __restrict__ bk){
    __shared__ float As[16][65], Bs[16][65];
    const int bm = blockIdx.x*64, bn = blockIdx.y*64, tid = threadIdx.x;
    const int tm = (tid/16)*4, tn = (tid%16)*4;
    float acc[4][4] = {};
    for(int k0=0;k0<Hv;k0+=16){
        for(int i=tid;i<64*16;i+=NTHR){
            int m=i>>4,k=i&15;
            As[k][m]=enc[(size_t)(bm+m)*Hv+k0+k];
            Bs[k][m]=Wk [(size_t)(bn+m)*Hv+k0+k];
        }
        __syncthreads();
#pragma unroll
        for(int k=0;k<16;k++){
            float a[4],b[4];
#pragma unroll
            for(int x=0;x<4;x++){ a[x]=As[k][tm+x]; b[x]=Bs[k][tn+x]; }
#pragma unroll
            for(int x=0;x<4;x++)
#pragma unroll
                for(int y=0;y<4;y++) acc[x][y]+=a[x]*b[y];
        }
        __syncthreads();
    }
#pragma unroll
    for(int x=0;x<4;x++)
#pragma unroll
        for(int y=0;y<4;y++)
            g_Kproj[(size_t)(bm+tm+x)*Hv+bn+tn+y]=acc[x][y]+bk[bn+tn+y];
}

// ---------- init ----------
__global__ void decoder_init(const float* __restrict__ h0in,
                             const float* __restrict__ Wq, const float* __restrict__ bq){
    const int tid=threadIdx.x, blk=blockIdx.x, gid=blk*NTHR+tid;
    if(gid<Bv*Hv){
        g_h[0][0][gid]=h0in[gid];
        g_h[1][0][gid]=h0in[Bv*Hv+gid];
        g_ctx[0][gid]=0.f; g_ctx[1][gid]=0.f;
    }
    if(gid<64){ g_cnt2[gid]=0u; g_gen2[gid]=0u; }
    if(gid>=64 && gid<64+Bv){ g_scnt[gid-64]=0u; g_sgen[gid-64]=0u; }
    const int ab=blk>>3, sub=blk&7, wid=tid>>5, lane=tid&31;
    const float4* h14=(const float4*)(h0in+Bv*Hv+ab*Hv);
#pragma unroll
    for(int r=0;r<8;r++){
        const int hrow=sub*64+r*8+wid;
        const float4* wr=(const float4*)(Wq+(size_t)hrow*Hv);
        float acc=0.f;
#pragma unroll
        for(int i=0;i<4;i++){
            float4 w4=wr[i*32+lane], x4=h14[i*32+lane];
            acc+=w4.x*x4.x+w4.y*x4.y+w4.z*x4.z+w4.w*x4.w;
        }
        acc=warp_sum(acc);
        if(lane==0) g_qp[ab*Hv+hrow]=acc+bq[hrow];
    }
}

// ---------- persistent decoder: two independent warpgroup pipelines ----------
__global__ void __launch_bounds__(NTHR,1)
decoder_main(const float* __restrict__ enc, const float* __restrict__ c0in,
             const float* __restrict__ Wq, const float* __restrict__ bq,
             const float* __restrict__ v,  const float* __restrict__ vb,
             const float* __restrict__ Wih0, const float* __restrict__ bih0,
             const float* __restrict__ Whh0, const float* __restrict__ bhh0,
             const float* __restrict__ Wih1, const float* __restrict__ bih1,
             const float* __restrict__ Whh1, const float* __restrict__ bhh1,
             const float* __restrict__ Wout, const float* __restrict__ bout,
             float* __restrict__ out){
    extern __shared__ float sm[];
    float4* smW0 = (float4*)(sm + SM_W0);
    float4* smW1 = (float4*)(sm + SM_W1);

    const int tid=threadIdx.x, blk=blockIdx.x;
    const int wg = tid>>7, wg_tid = tid&127;
    const int wwid = wg_tid>>5, wlane = wg_tid&31;

    // ---- prologue (whole block cooperates, one __syncthreads) ----
    for(int idx=tid; idx<16*384; idx+=NTHR){
        const int slot=idx/384, c=idx-slot*384;
        const int u=slot>>2, g=slot&3;
        const int grow=g*512+blk*4+u;
        float4 val = (c<256)? ((const float4*)Wih0)[(size_t)grow*256+c]
                            : ((const float4*)Whh0)[(size_t)grow*128+(c-256)];
        smW0[slot*385+c]=val;
    }
    for(int idx=tid; idx<16*256; idx+=NTHR){
        const int slot=idx>>8, c=idx&255;
        const int u=slot>>2, g=slot&3;
        const int grow=g*512+blk*4+u;
        float4 val = (c<128)? ((const float4*)Wih1)[(size_t)grow*128+c]
                            : ((const float4*)Whh1)[(size_t)grow*128+(c-128)];
        smW1[slot*257+c]=val;
    }
    sm[SM_SV+tid]=v[tid]; sm[SM_SV+tid+256]=v[tid+256];
    const float vb0=vb[0];

    // WG-scoped constants
    const int ab = wg*8 + (blk>>4);            // attention batch of this block-WG
    const int sub16 = blk&15, t0 = sub16*16;   // t-chunk of 16
    const int kc = wg_tid>>3, rg = (wg_tid>>1)&3, bg = wg_tid&1;   // GEMV coords
    const int kc24 = kc*24, kc16 = kc*16;
    const int r16 = wg_tid>>3, b8r = wg_tid&7; // reduction cell
    const int growB=(r16>>2)*512+blk*4+(r16&3);
    const float bs0=bih0[growB]+bhh0[growB];
    const float bs1=bih1[growB]+bhh1[growB];
    (void)b8r;
    // cell ownership: wg_tid<32: unit=blk*4+(wg_tid>>3), batch=wg*8+(wg_tid&7)
    const int ulc=wg_tid>>3, b8c=wg_tid&7, bglobc=wg*8+b8c, unitc=blk*4+ulc;
    float c0r=0.f, c1r=0.f;
    if(wg_tid<32){
        c0r=c0in[bglobc*Hv+unitc];
        c1r=c0in[Bv*Hv+bglobc*Hv+unitc];
    }
    float* redw = sm + SM_RED + wg*2048;
    float* sgw  = sm + SM_SG  + wg*128;
    float* sqw  = sm + SM_SQ  + wg*512;
    float* sww  = sm + SM_SW  + wg*16;
    float* sstw = sm + SM_SST + wg*2;
    __syncthreads();

    unsigned bar_k=1, sub_k=1;

    for(int s=0;s<Tv;s++){
        const int p=s&1, pn=p^1;

        // ======== P1: attention scores for (ab, t0..t0+15) ========
        ((float4*)sqw)[wg_tid] = ((const float4*)(g_qp+ab*Hv))[wg_tid];
        wg_bar(wg);
        {
            const float4* sq4=(const float4*)sqw;
            const float4* sv4=(const float4*)(sm+SM_SV);
            const float4* kp[4];
#pragma unroll
            for(int r=0;r<4;r++)
                kp[r]=(const float4*)(g_Kproj+(size_t)(ab*Tv+t0+wwid*4+r)*Hv);
            float acc[4]={};
#pragma unroll
            for(int i=0;i<4;i++){
                float4 q4=sq4[i*32+wlane], vv=sv4[i*32+wlane];
#pragma unroll
                for(int r=0;r<4;r++){
                    float4 k4=kp[r][i*32+wlane];
                    acc[r]+=vv.x*tanha(q4.x+k4.x)+vv.y*tanha(q4.y+k4.y)
                          +vv.z*tanha(q4.z+k4.z)+vv.w*tanha(q4.w+k4.w);
                }
            }
#pragma unroll
            for(int r=0;r<4;r++){
                float sres=warp_sum(acc[r]);
                if(wlane==0) g_scores[ab*Tv+t0+wwid*4+r]=sres+vb0;
            }
        }
        sub_barrier16(sub_k, wg, wg_tid, ab); sub_k++;

        // ======== P2: softmax + partial ctx ========
        if(wwid==0){
            float scv[8], m=-1e30f;
#pragma unroll
            for(int j=0;j<8;j++){ scv[j]=g_scores[ab*Tv+wlane+j*32]; m=fmaxf(m,scv[j]); }
            m=warp_max(m);
            float su=0.f;
#pragma unroll
            for(int j=0;j<8;j++) su+=expf(scv[j]-m);
            su=warp_sum(su);
            if(wlane==0){ sstw[0]=m; sstw[1]=su; }
        }
        if(wg_tid<32) g_ctx[pn][wg*4096 + blk*32 + wg_tid]=0.f;  // own WG-set's batches only
        wg_bar(wg);
        if(wg_tid<16) sww[wg_tid]=expf(g_scores[ab*Tv+t0+wg_tid]-sstw[0])/sstw[1];
        wg_bar(wg);
        {
            const int h4=wg_tid*4;
            float a0=0.f,a1=0.f,a2=0.f,a3=0.f;
#pragma unroll 4
            for(int j=0;j<16;j++){
                const float wj=sww[j];
                const float4 e4=*(const float4*)(enc+(size_t)(ab*Tv+t0+j)*Hv+h4);
                a0+=wj*e4.x; a1+=wj*e4.y; a2+=wj*e4.z; a3+=wj*e4.w;
            }
            float* cdst=&g_ctx[p][ab*Hv+h4];
            atomicAdd(cdst,a0); atomicAdd(cdst+1,a1);
            atomicAdd(cdst+2,a2); atomicAdd(cdst+3,a3);
        }
        grid_barrier_wg(bar_k, wg, wg_tid); bar_k++;

        // ======== P3: LSTM layer 0, K=1536 (weights LDS, x direct-global) ========
        {
            const float4* ep[4];
#pragma unroll
            for(int j=0;j<4;j++)
                ep[j]=(const float4*)(enc+((size_t)((wg*8+bg*4+j)*Tv+s))*Hv);
            const float4* cp=(const float4*)g_ctx[p];
            const float4* hp=(const float4*)g_h[0][p];
            float acc[4][4]={};
#pragma unroll 8
            for(int k4=0;k4<24;k4++){
                const int kg=kc24+k4;
                float4 xv[4];
#pragma unroll
                for(int j=0;j<4;j++){
                    const int b_=wg*8+bg*4+j;
                    xv[j]=(kg<128)? ep[j][kg]
                         :(kg<256)? cp[b_*128+(kg-128)]
                                  : hp[b_*128+(kg-256)];
                }
                float4 wv[4];
#pragma unroll
                for(int i=0;i<4;i++) wv[i]=smW0[(i*4+rg)*385+kg];
#pragma unroll
                for(int i=0;i<4;i++)
#pragma unroll
                    for(int j=0;j<4;j++)
                        acc[i][j]+=wv[i].x*xv[j].x+wv[i].y*xv[j].y+wv[i].z*xv[j].z+wv[i].w*xv[j].w;
            }
            float* red = redw+kc*128;
#pragma unroll
            for(int i=0;i<4;i++)
                *(float4*)(red+(rg*4+i)*8+bg*4)=make_float4(acc[i][0],acc[i][1],acc[i][2],acc[i][3]);
        }
        wg_bar(wg);
        {
            float g=0.f;
#pragma unroll
            for(int kk=0;kk<16;kk++) g+=redw[kk*128+wg_tid];
            sgw[wg_tid]=g+bs0;
        }
        wg_bar(wg);
        if(wg_tid<32){
            const float gi=sgw[(0+ulc)*8+b8c], gf=sgw[(4+ulc)*8+b8c];
            const float gg=sgw[(8+ulc)*8+b8c], go=sgw[(12+ulc)*8+b8c];
            c0r=sigf(gf)*c0r+sigf(gi)*tanhf(gg);
            g_h[0][pn][bglobc*Hv+unitc]=sigf(go)*tanhf(c0r);
        }
        grid_barrier_wg(bar_k, wg, wg_tid); bar_k++;

        // ======== P4: LSTM layer 1, K=1024 ========
        {
            const float4* h0n=(const float4*)g_h[0][pn];
            const float4* h1o=(const float4*)g_h[1][p];
            float acc[4][4]={};
#pragma unroll 8
            for(int k4=0;k4<16;k4++){
                const int kg=kc16+k4;
                float4 xv[4];
#pragma unroll
                for(int j=0;j<4;j++){
                    const int b_=wg*8+bg*4+j;
                    xv[j]=(kg<128)? h0n[b_*128+kg] : h1o[b_*128+(kg-128)];
                }
                float4 wv[4];
#pragma unroll
                for(int i=0;i<4;i++) wv[i]=smW1[(i*4+rg)*257+kg];
#pragma unroll
                for(int i=0;i<4;i++)
#pragma unroll
                    for(int j=0;j<4;j++)
                        acc[i][j]+=wv[i].x*xv[j].x+wv[i].y*xv[j].y+wv[i].z*xv[j].z+wv[i].w*xv[j].w;
            }
            float* red = redw+kc*128;
#pragma unroll
            for(int i=0;i<4;i++)
                *(float4*)(red+(rg*4+i)*8+bg*4)=make_float4(acc[i][0],acc[i][1],acc[i][2],acc[i][3]);
        }
        wg_bar(wg);
        {
            float g=0.f;
#pragma unroll
            for(int kk=0;kk<16;kk++) g+=redw[kk*128+wg_tid];
            sgw[wg_tid]=g+bs1;
        }
        wg_bar(wg);
        if(wg_tid<32){
            const float gi=sgw[(0+ulc)*8+b8c], gf=sgw[(4+ulc)*8+b8c];
            const float gg=sgw[(8+ulc)*8+b8c], go=sgw[(12+ulc)*8+b8c];
            c1r=sigf(gf)*c1r+sigf(gi)*tanhf(gg);
            g_h[1][pn][bglobc*Hv+unitc]=sigf(go)*tanhf(c1r);
        }
        grid_barrier_wg(bar_k, wg, wg_tid); bar_k++;

        // ======== P5: qp (next step) + logits for batch ab ========
        {
            float4* st4=(float4*)redw;
            st4[wg_tid]=((const float4*)g_h[1][pn])[ab*128+wg_tid];
            wg_bar(wg);
#pragma unroll
            for(int jj=0;jj<2;jj++){
                float acc[4]={};
#pragma unroll
                for(int i=0;i<4;i++){
                    float4 x4=st4[i*32+wlane];
#pragma unroll
                    for(int r=0;r<4;r++){
                        const int h=sub16*32+wwid*8+jj*4+r;
                        float4 w4=((const float4*)(Wq+(size_t)h*Hv))[i*32+wlane];
                        acc[r]+=w4.x*x4.x+w4.y*x4.y+w4.z*x4.z+w4.w*x4.w;
                    }
                }
#pragma unroll
                for(int r=0;r<4;r++){
                    float sres=warp_sum(acc[r]);
                    const int h=sub16*32+wwid*8+jj*4+r;
                    if(wlane==0) g_qp[ab*Hv+h]=sres+bq[h];
                }
            }
            if(wwid<2){
                const int vo=sub16*2+wwid;
                const float4* wo4=(const float4*)(Wout+(size_t)vo*Hv);
                float acc=0.f;
#pragma unroll
                for(int i=0;i<4;i++){
                    float4 w4=wo4[i*32+wlane], x4=st4[i*32+wlane];
                    acc+=w4.x*x4.x+w4.y*x4.y+w4.z*x4.z+w4.w*x4.w;
                }
                acc=warp_sum(acc);
                if(wlane==0) out[(size_t)(ab*Tv+s)*Vv+vo]=acc+bout[vo];
            }
        }
        sub_barrier16(sub_k, wg, wg_tid, ab); sub_k++;
    }
}

extern "C" void kernel_launch(void* const* d_in, const int* in_sizes, int n_in,
                              void* d_out, int out_size){
    const float* enc  =(const float*)d_in[0];
    const float* h0in =(const float*)d_in[1];
    const float* c0in =(const float*)d_in[2];
    const float* Wq   =(const float*)d_in[4];
    const float* bq   =(const float*)d_in[5];
    const float* Wk   =(const float*)d_in[6];
    const float* bk   =(const float*)d_in[7];
    const float* v    =(const float*)d_in[8];
    const float* vb   =(const float*)d_in[9];
    const float* Wih0 =(const float*)d_in[10];
    const float* bih0 =(const float*)d_in[11];
    const float* Whh0 =(const float*)d_in[12];
    const float* bhh0 =(const float*)d_in[13];
    const float* Wih1 =(const float*)d_in[14];
    const float* bih1 =(const float*)d_in[15];
    const float* Whh1 =(const float*)d_in[16];
    const float* bhh1 =(const float*)d_in[17];
    const float* Wout =(const float*)d_in[18];
    const float* bout =(const float*)d_in[19];
    float* out=(float*)d_out;

    const int smem_bytes = SMEM_FLOATS*4;
    cudaFuncSetAttribute(decoder_main, cudaFuncAttributeMaxDynamicSharedMemorySize, smem_bytes);

    kproj_kernel<<<dim3(64,8),NTHR>>>(enc,Wk,bk);
    decoder_init<<<NBLK,NTHR>>>(h0in,Wq,bq);
    decoder_main<<<NBLK,NTHR,smem_bytes>>>(enc,c0in,Wq,bq,v,vb,
        Wih0,bih0,Whh0,bhh0,Wih1,bih1,Whh1,bhh1,Wout,bout,out);
}

// round 10
// speedup vs baseline: 1.6517x; 1.2717x over previous
#include <cuda_runtime.h>
#include <math.h>

#define Bv 16
#define Tv 256
#define Hv 512
#define Vv 32
#define NBLK 128
#define NTHR 256

// smem layout (floats)
#define SM_W0   0                       // 16 slots * 385 float4 = 24640 f
#define SM_W1   24640                   // 16 slots * 257 float4 = 16448 f
#define SM_RED  41088                   // 2 WG * 2048 f (also P5 h1 stage)
#define SM_SG   45184                   // 2 * 128
#define SM_SQ   45440                   // 2 * 512
#define SM_SV   46464                   // 512 (shared)
#define SM_SW   46976                   // 2 * 16
#define SM_SST  47008                   // 2 * 2
#define SMEM_FLOATS 47012               // 188048 bytes

__device__ float g_Kproj[Bv*Tv*Hv];
__device__ float g_qp[Bv*Hv];
__device__ float g_scores[Bv*Tv];
__device__ float g_ctx[2][Bv*Hv];
__device__ float g_h[2][2][Bv*Hv];      // [layer][parity][b*H+h]
__device__ unsigned g_cnt2[2*32];       // per-WG-set barrier counter (padded)
__device__ unsigned g_gen2[2*32];       // per-WG-set generation (padded)
__device__ unsigned g_scnt[Bv];         // per-batch sub-barrier counters
__device__ unsigned g_sgen[Bv];

__device__ __forceinline__ float warp_sum(float v){
#pragma unroll
    for(int o=16;o>0;o>>=1) v += __shfl_xor_sync(0xffffffffu,v,o);
    return v;
}
__device__ __forceinline__ float warp_max(float v){
#pragma unroll
    for(int o=16;o>0;o>>=1) v = fmaxf(v,__shfl_xor_sync(0xffffffffu,v,o));
    return v;
}
__device__ __forceinline__ float sigf(float x){ return 1.0f/(1.0f+expf(-x)); }
__device__ __forceinline__ float tanha(float x){ float y; asm("tanh.approx.f32 %0,%1;":"=f"(y):"f"(x)); return y; }
__device__ __forceinline__ unsigned ld_acq(const unsigned* p){
    unsigned v; asm volatile("ld.acquire.gpu.global.u32 %0,[%1];":"=r"(v):"l"(p):"memory"); return v;
}
__device__ __forceinline__ unsigned atom_add_acqrel(unsigned* p, unsigned v){
    unsigned old; asm volatile("atom.acq_rel.gpu.global.add.u32 %0,[%1],%2;":"=r"(old):"l"(p),"r"(v):"memory"); return old;
}
__device__ __forceinline__ void st_rel(unsigned* p, unsigned v){
    asm volatile("st.release.gpu.global.u32 [%0],%1;"::"l"(p),"r"(v):"memory");
}
__device__ __forceinline__ void wg_bar(int wg){
    asm volatile("bar.sync %0,%1;"::"r"(1+wg),"r"(128):"memory");
}
// split-phase grid barrier pieces
__device__ __forceinline__ void gb_arrive(unsigned k, int wg, int wg_tid){
    if(wg_tid==0){
        unsigned old = atom_add_acqrel(&g_cnt2[wg*32], 1u);
        if(old == k*(unsigned)NBLK - 1u) st_rel(&g_gen2[wg*32], k);
    }
}
__device__ __forceinline__ void gb_wait(unsigned k, int wg, int wg_tid){
    if(wg_tid==0){
        while(ld_acq(&g_gen2[wg*32]) < k) __nanosleep(32);
    }
    wg_bar(wg);
}
__device__ __forceinline__ void sub_barrier16(unsigned k, int wg, int wg_tid, int b){
    wg_bar(wg);
    if(wg_tid==0){
        unsigned old = atom_add_acqrel(&g_scnt[b], 1u);
        if(old == k*16u - 1u) st_rel(&g_sgen[b], k);
        while(ld_acq(&g_sgen[b]) < k) __nanosleep(32);
    }
    wg_bar(wg);
}

// ---------- Kproj = enc @ Wk^T + bk ----------
__global__ void kproj_kernel(const float* __restrict__ enc, const float* __restrict__ Wk,
                             const float* __restrict__ bk){
    __shared__ float As[16][65], Bs[16][65];
    const int bm = blockIdx.x*64, bn = blockIdx.y*64, tid = threadIdx.x;
    const int tm = (tid/16)*4, tn = (tid%16)*4;
    float acc[4][4] = {};
    for(int k0=0;k0<Hv;k0+=16){
        for(int i=tid;i<64*16;i+=NTHR){
            int m=i>>4,k=i&15;
            As[k][m]=enc[(size_t)(bm+m)*Hv+k0+k];
            Bs[k][m]=Wk [(size_t)(bn+m)*Hv+k0+k];
        }
        __syncthreads();
#pragma unroll
        for(int k=0;k<16;k++){
            float a[4],b[4];
#pragma unroll
            for(int x=0;x<4;x++){ a[x]=As[k][tm+x]; b[x]=Bs[k][tn+x]; }
#pragma unroll
            for(int x=0;x<4;x++)
#pragma unroll
                for(int y=0;y<4;y++) acc[x][y]+=a[x]*b[y];
        }
        __syncthreads();
    }
#pragma unroll
    for(int x=0;x<4;x++)
#pragma unroll
        for(int y=0;y<4;y++)
            g_Kproj[(size_t)(bm+tm+x)*Hv+bn+tn+y]=acc[x][y]+bk[bn+tn+y];
}

// ---------- init ----------
__global__ void decoder_init(const float* __restrict__ h0in,
                             const float* __restrict__ Wq, const float* __restrict__ bq){
    const int tid=threadIdx.x, blk=blockIdx.x, gid=blk*NTHR+tid;
    if(gid<Bv*Hv){
        g_h[0][0][gid]=h0in[gid];
        g_h[1][0][gid]=h0in[Bv*Hv+gid];
        g_ctx[0][gid]=0.f; g_ctx[1][gid]=0.f;
    }
    if(gid<64){ g_cnt2[gid]=0u; g_gen2[gid]=0u; }
    if(gid>=64 && gid<64+Bv){ g_scnt[gid-64]=0u; g_sgen[gid-64]=0u; }
    const int ab=blk>>3, sub=blk&7, wid=tid>>5, lane=tid&31;
    const float4* h14=(const float4*)(h0in+Bv*Hv+ab*Hv);
#pragma unroll
    for(int r=0;r<8;r++){
        const int hrow=sub*64+r*8+wid;
        const float4* wr=(const float4*)(Wq+(size_t)hrow*Hv);
        float acc=0.f;
#pragma unroll
        for(int i=0;i<4;i++){
            float4 w4=wr[i*32+lane], x4=h14[i*32+lane];
            acc+=w4.x*x4.x+w4.y*x4.y+w4.z*x4.z+w4.w*x4.w;
        }
        acc=warp_sum(acc);
        if(lane==0) g_qp[ab*Hv+hrow]=acc+bq[hrow];
    }
}

// ---------- persistent decoder: dual-WG pipelines + split-phase barriers ----------
__global__ void __launch_bounds__(NTHR,1)
decoder_main(const float* __restrict__ enc, const float* __restrict__ c0in,
             const float* __restrict__ Wq, const float* __restrict__ bq,
             const float* __restrict__ v,  const float* __restrict__ vb,
             const float* __restrict__ Wih0, const float* __restrict__ bih0,
             const float* __restrict__ Whh0, const float* __restrict__ bhh0,
             const float* __restrict__ Wih1, const float* __restrict__ bih1,
             const float* __restrict__ Whh1, const float* __restrict__ bhh1,
             const float* __restrict__ Wout, const float* __restrict__ bout,
             float* __restrict__ out){
    extern __shared__ float sm[];
    float4* smW0 = (float4*)(sm + SM_W0);
    float4* smW1 = (float4*)(sm + SM_W1);

    const int tid=threadIdx.x, blk=blockIdx.x;
    const int wg = tid>>7, wg_tid = tid&127;
    const int wwid = wg_tid>>5, wlane = wg_tid&31;

    // ---- prologue ----
    for(int idx=tid; idx<16*384; idx+=NTHR){
        const int slot=idx/384, c=idx-slot*384;
        const int u=slot>>2, g=slot&3;
        const int grow=g*512+blk*4+u;
        float4 val = (c<256)? ((const float4*)Wih0)[(size_t)grow*256+c]
                            : ((const float4*)Whh0)[(size_t)grow*128+(c-256)];
        smW0[slot*385+c]=val;
    }
    for(int idx=tid; idx<16*256; idx+=NTHR){
        const int slot=idx>>8, c=idx&255;
        const int u=slot>>2, g=slot&3;
        const int grow=g*512+blk*4+u;
        float4 val = (c<128)? ((const float4*)Wih1)[(size_t)grow*128+c]
                            : ((const float4*)Whh1)[(size_t)grow*128+(c-128)];
        smW1[slot*257+c]=val;
    }
    sm[SM_SV+tid]=v[tid]; sm[SM_SV+tid+256]=v[tid+256];
    const float vb0=vb[0];

    const int ab = wg*8 + (blk>>4);
    const int sub16 = blk&15, t0 = sub16*16;
    const int kc = wg_tid>>3, rg = (wg_tid>>1)&3, bg = wg_tid&1;
    const int r16 = wg_tid>>3;
    const int growB=(r16>>2)*512+blk*4+(r16&3);
    const float bs0=bih0[growB]+bhh0[growB];
    const float bs1=bih1[growB]+bhh1[growB];
    const int ulc=wg_tid>>3, b8c=wg_tid&7, bglobc=wg*8+b8c, unitc=blk*4+ulc;
    float c0r=0.f, c1r=0.f;
    if(wg_tid<32){
        c0r=c0in[bglobc*Hv+unitc];
        c1r=c0in[Bv*Hv+bglobc*Hv+unitc];
    }
    float* redw = sm + SM_RED + wg*2048;
    float* sgw  = sm + SM_SG  + wg*128;
    float* sqw  = sm + SM_SQ  + wg*512;
    float* sww  = sm + SM_SW  + wg*16;
    float* sstw = sm + SM_SST + wg*2;
    __syncthreads();

    unsigned bar_k=1, sub_k=1;

    for(int s=0;s<Tv;s++){
        const int p=s&1, pn=p^1;

        // ======== P1: attention scores for (ab, t0..t0+15) ========
        ((float4*)sqw)[wg_tid] = ((const float4*)(g_qp+ab*Hv))[wg_tid];
        wg_bar(wg);
        {
            const float4* sq4=(const float4*)sqw;
            const float4* sv4=(const float4*)(sm+SM_SV);
            const float4* kp[4];
#pragma unroll
            for(int r=0;r<4;r++)
                kp[r]=(const float4*)(g_Kproj+(size_t)(ab*Tv+t0+wwid*4+r)*Hv);
            float acc[4]={};
#pragma unroll
            for(int i=0;i<4;i++){
                float4 q4=sq4[i*32+wlane], vv=sv4[i*32+wlane];
#pragma unroll
                for(int r=0;r<4;r++){
                    float4 k4=kp[r][i*32+wlane];
                    acc[r]+=vv.x*tanha(q4.x+k4.x)+vv.y*tanha(q4.y+k4.y)
                          +vv.z*tanha(q4.z+k4.z)+vv.w*tanha(q4.w+k4.w);
                }
            }
#pragma unroll
            for(int r=0;r<4;r++){
                float sres=warp_sum(acc[r]);
                if(wlane==0) g_scores[ab*Tv+t0+wwid*4+r]=sres+vb0;
            }
        }
        sub_barrier16(sub_k, wg, wg_tid, ab); sub_k++;

        // ======== P2: softmax + partial ctx ========
        if(wwid==0){
            float scv[8], m=-1e30f;
#pragma unroll
            for(int j=0;j<8;j++){ scv[j]=g_scores[ab*Tv+wlane+j*32]; m=fmaxf(m,scv[j]); }
            m=warp_max(m);
            float su=0.f;
#pragma unroll
            for(int j=0;j<8;j++) su+=expf(scv[j]-m);
            su=warp_sum(su);
            if(wlane==0){ sstw[0]=m; sstw[1]=su; }
        }
        if(wg_tid<32) g_ctx[pn][wg*4096 + blk*32 + wg_tid]=0.f;
        wg_bar(wg);
        if(wg_tid<16) sww[wg_tid]=expf(g_scores[ab*Tv+t0+wg_tid]-sstw[0])/sstw[1];
        wg_bar(wg);
        {
            const int h4=wg_tid*4;
            float a0=0.f,a1=0.f,a2=0.f,a3=0.f;
#pragma unroll 4
            for(int j=0;j<16;j++){
                const float wj=sww[j];
                const float4 e4=*(const float4*)(enc+(size_t)(ab*Tv+t0+j)*Hv+h4);
                a0+=wj*e4.x; a1+=wj*e4.y; a2+=wj*e4.z; a3+=wj*e4.w;
            }
            float* cdst=&g_ctx[p][ab*Hv+h4];
            atomicAdd(cdst,a0); atomicAdd(cdst+1,a1);
            atomicAdd(cdst+2,a2); atomicAdd(cdst+3,a3);
        }

        // ======== barrier A (split-phase) + P3 ========
        wg_bar(wg);
        gb_arrive(bar_k, wg, wg_tid);
        float acc[4][4]={};
        // --- P3a: enc (kc<8) or h0_old (kc>=8) part, 16 k4 each ---
        if(kc<8){
            const float4* ep[4];
#pragma unroll
            for(int j=0;j<4;j++)
                ep[j]=(const float4*)(enc+((size_t)((wg*8+bg*4+j)*Tv+s))*Hv);
#pragma unroll 8
            for(int k4=0;k4<16;k4++){
                const int kgw=kc*16+k4;
                float4 xv[4], wv[4];
#pragma unroll
                for(int j=0;j<4;j++) xv[j]=ep[j][kgw];
#pragma unroll
                for(int i=0;i<4;i++) wv[i]=smW0[(i*4+rg)*385+kgw];
#pragma unroll
                for(int i=0;i<4;i++)
#pragma unroll
                    for(int j=0;j<4;j++)
                        acc[i][j]+=wv[i].x*xv[j].x+wv[i].y*xv[j].y+wv[i].z*xv[j].z+wv[i].w*xv[j].w;
            }
        }else{
            const float4* hp=(const float4*)g_h[0][p];
#pragma unroll 8
            for(int k4=0;k4<16;k4++){
                const int kk=(kc-8)*16+k4;
                float4 xv[4], wv[4];
#pragma unroll
                for(int j=0;j<4;j++) xv[j]=hp[(wg*8+bg*4+j)*128+kk];
#pragma unroll
                for(int i=0;i<4;i++) wv[i]=smW0[(i*4+rg)*385+256+kk];
#pragma unroll
                for(int i=0;i<4;i++)
#pragma unroll
                    for(int j=0;j<4;j++)
                        acc[i][j]+=wv[i].x*xv[j].x+wv[i].y*xv[j].y+wv[i].z*xv[j].z+wv[i].w*xv[j].w;
            }
        }
        gb_wait(bar_k, wg, wg_tid); bar_k++;
        // --- P3b: ctx part, 8 k4 ---
        {
            const float4* cp=(const float4*)g_ctx[p];
#pragma unroll 8
            for(int k4=0;k4<8;k4++){
                const int kk=kc*8+k4;
                float4 xv[4], wv[4];
#pragma unroll
                for(int j=0;j<4;j++) xv[j]=cp[(wg*8+bg*4+j)*128+kk];
#pragma unroll
                for(int i=0;i<4;i++) wv[i]=smW0[(i*4+rg)*385+128+kk];
#pragma unroll
                for(int i=0;i<4;i++)
#pragma unroll
                    for(int j=0;j<4;j++)
                        acc[i][j]+=wv[i].x*xv[j].x+wv[i].y*xv[j].y+wv[i].z*xv[j].z+wv[i].w*xv[j].w;
            }
            float* red = redw+kc*128;
#pragma unroll
            for(int i=0;i<4;i++)
                *(float4*)(red+(rg*4+i)*8+bg*4)=make_float4(acc[i][0],acc[i][1],acc[i][2],acc[i][3]);
        }
        wg_bar(wg);
        {
            float g=0.f;
#pragma unroll
            for(int kk=0;kk<16;kk++) g+=redw[kk*128+wg_tid];
            sgw[wg_tid]=g+bs0;
        }
        wg_bar(wg);
        if(wg_tid<32){
            const float gi=sgw[(0+ulc)*8+b8c], gf=sgw[(4+ulc)*8+b8c];
            const float gg=sgw[(8+ulc)*8+b8c], go=sgw[(12+ulc)*8+b8c];
            c0r=sigf(gf)*c0r+sigf(gi)*tanhf(gg);
            g_h[0][pn][bglobc*Hv+unitc]=sigf(go)*tanhf(c0r);
        }

        // ======== barrier B (split-phase) + P4 ========
        wg_bar(wg);
        gb_arrive(bar_k, wg, wg_tid);
        float acc4[4][4]={};
        // --- P4a: h1_old part, 8 k4 ---
        {
            const float4* h1o=(const float4*)g_h[1][p];
#pragma unroll 8
            for(int k4=0;k4<8;k4++){
                const int kk=kc*8+k4;
                float4 xv[4], wv[4];
#pragma unroll
                for(int j=0;j<4;j++) xv[j]=h1o[(wg*8+bg*4+j)*128+kk];
#pragma unroll
                for(int i=0;i<4;i++) wv[i]=smW1[(i*4+rg)*257+128+kk];
#pragma unroll
                for(int i=0;i<4;i++)
#pragma unroll
                    for(int j=0;j<4;j++)
                        acc4[i][j]+=wv[i].x*xv[j].x+wv[i].y*xv[j].y+wv[i].z*xv[j].z+wv[i].w*xv[j].w;
            }
        }
        gb_wait(bar_k, wg, wg_tid); bar_k++;
        // --- P4b: h0_new part, 8 k4 ---
        {
            const float4* h0n=(const float4*)g_h[0][pn];
#pragma unroll 8
            for(int k4=0;k4<8;k4++){
                const int kk=kc*8+k4;
                float4 xv[4], wv[4];
#pragma unroll
                for(int j=0;j<4;j++) xv[j]=h0n[(wg*8+bg*4+j)*128+kk];
#pragma unroll
                for(int i=0;i<4;i++) wv[i]=smW1[(i*4+rg)*257+kk];
#pragma unroll
                for(int i=0;i<4;i++)
#pragma unroll
                    for(int j=0;j<4;j++)
                        acc4[i][j]+=wv[i].x*xv[j].x+wv[i].y*xv[j].y+wv[i].z*xv[j].z+wv[i].w*xv[j].w;
            }
            float* red = redw+kc*128;
#pragma unroll
            for(int i=0;i<4;i++)
                *(float4*)(red+(rg*4+i)*8+bg*4)=make_float4(acc4[i][0],acc4[i][1],acc4[i][2],acc4[i][3]);
        }
        wg_bar(wg);
        {
            float g=0.f;
#pragma unroll
            for(int kk=0;kk<16;kk++) g+=redw[kk*128+wg_tid];
            sgw[wg_tid]=g+bs1;
        }
        wg_bar(wg);
        if(wg_tid<32){
            const float gi=sgw[(0+ulc)*8+b8c], gf=sgw[(4+ulc)*8+b8c];
            const float gg=sgw[(8+ulc)*8+b8c], go=sgw[(12+ulc)*8+b8c];
            c1r=sigf(gf)*c1r+sigf(gi)*tanhf(gg);
            g_h[1][pn][bglobc*Hv+unitc]=sigf(go)*tanhf(c1r);
        }

        // ======== barrier C (plain) ========
        wg_bar(wg);
        gb_arrive(bar_k, wg, wg_tid);
        gb_wait(bar_k, wg, wg_tid); bar_k++;

        // ======== P5: qp (next step) + logits for batch ab ========
        {
            float4* st4=(float4*)redw;
            st4[wg_tid]=((const float4*)g_h[1][pn])[ab*128+wg_tid];
            wg_bar(wg);
#pragma unroll
            for(int jj=0;jj<2;jj++){
                float accq[4]={};
#pragma unroll
                for(int i=0;i<4;i++){
                    float4 x4=st4[i*32+wlane];
#pragma unroll
                    for(int r=0;r<4;r++){
                        const int h=sub16*32+wwid*8+jj*4+r;
                        float4 w4=((const float4*)(Wq+(size_t)h*Hv))[i*32+wlane];
                        accq[r]+=w4.x*x4.x+w4.y*x4.y+w4.z*x4.z+w4.w*x4.w;
                    }
                }
#pragma unroll
                for(int r=0;r<4;r++){
                    float sres=warp_sum(accq[r]);
                    const int h=sub16*32+wwid*8+jj*4+r;
                    if(wlane==0) g_qp[ab*Hv+h]=sres+bq[h];
                }
            }
            if(wwid<2){
                const int vo=sub16*2+wwid;
                const float4* wo4=(const float4*)(Wout+(size_t)vo*Hv);
                float acco=0.f;
#pragma unroll
                for(int i=0;i<4;i++){
                    float4 w4=wo4[i*32+wlane], x4=st4[i*32+wlane];
                    acco+=w4.x*x4.x+w4.y*x4.y+w4.z*x4.z+w4.w*x4.w;
                }
                acco=warp_sum(acco);
                if(wlane==0) out[(size_t)(ab*Tv+s)*Vv+vo]=acco+bout[vo];
            }
        }
        sub_barrier16(sub_k, wg, wg_tid, ab); sub_k++;
    }
}

extern "C" void kernel_launch(void* const* d_in, const int* in_sizes, int n_in,
                              void* d_out, int out_size){
    const float* enc  =(const float*)d_in[0];
    const float* h0in =(const float*)d_in[1];
    const float* c0in =(const float*)d_in[2];
    const float* Wq   =(const float*)d_in[4];
    const float* bq   =(const float*)d_in[5];
    const float* Wk   =(const float*)d_in[6];
    const float* bk   =(const float*)d_in[7];
    const float* v    =(const float*)d_in[8];
    const float* vb   =(const float*)d_in[9];
    const float* Wih0 =(const float*)d_in[10];
    const float* bih0 =(const float*)d_in[11];
    const float* Whh0 =(const float*)d_in[12];
    const float* bhh0 =(const float*)d_in[13];
    const float* Wih1 =(const float*)d_in[14];
    const float* bih1 =(const float*)d_in[15];
    const float* Whh1 =(const float*)d_in[16];
    const float* bhh1 =(const float*)d_in[17];
    const float* Wout =(const float*)d_in[18];
    const float* bout =(const float*)d_in[19];
    float* out=(float*)d_out;

    const int smem_bytes = SMEM_FLOATS*4;
    cudaFuncSetAttribute(decoder_main, cudaFuncAttributeMaxDynamicSharedMemorySize, smem_bytes);

    kproj_kernel<<<dim3(64,8),NTHR>>>(enc,Wk,bk);
    decoder_init<<<NBLK,NTHR>>>(h0in,Wq,bq);
    decoder_main<<<NBLK,NTHR,smem_bytes>>>(enc,c0in,Wq,bq,v,vb,
        Wih0,bih0,Whh0,bhh0,Wih1,bih1,Whh1,bhh1,Wout,bout,out);
}